// round 16
// baseline (speedup 1.0000x reference)
#include <cuda_runtime.h>
#include <cuda_fp16.h>
#include <math.h>
#include <stdint.h>

#define HDIM 2048
#define NEXP 16
#define IDIM 768
#define TWO_I 1536
#define TMAX 2048
#define PMAX (TMAX*2)

typedef unsigned short ushort_t;

// ---------------- device scratch ----------------
__device__ int   g_count[NEXP];
__device__ int   g_segstart[NEXP + 1];
__device__ int   g_tok_e[TMAX * 2];
__device__ float g_tok_w[TMAX * 2];
__device__ int   g_pair_token[PMAX];
__device__ float g_pair_w[PMAX];
__device__ __align__(16) ushort_t g_x_hi[(size_t)TMAX * HDIM];
__device__ __align__(16) ushort_t g_x_lo[(size_t)TMAX * HDIM];
__device__ __align__(16) ushort_t g_h_hi[(size_t)PMAX * IDIM];
__device__ __align__(16) ushort_t g_h_lo[(size_t)PMAX * IDIM];
__device__ float g_logits_fallback[TMAX * NEXP];

// ---------------- portable PTX helpers ----------------
__device__ __forceinline__ uint32_t smem_u32(const void* p) {
    uint32_t a;
    asm("{ .reg .u64 t; cvta.to.shared.u64 t, %1; cvt.u32.u64 %0, t; }" : "=r"(a) : "l"(p));
    return a;
}
#define LDMX4(r, addr) \
    asm volatile("ldmatrix.sync.aligned.m8n8.x4.shared.b16 {%0,%1,%2,%3}, [%4];" \
        : "=r"((r)[0]), "=r"((r)[1]), "=r"((r)[2]), "=r"((r)[3]) : "r"(addr))
#define MMA(acc, a, b0, b1) \
    asm volatile("mma.sync.aligned.m16n8k16.row.col.f32.f16.f16.f32 " \
        "{%0,%1,%2,%3}, {%4,%5,%6,%7}, {%8,%9}, {%0,%1,%2,%3};" \
        : "+f"((acc)[0]), "+f"((acc)[1]), "+f"((acc)[2]), "+f"((acc)[3]) \
        : "r"((a)[0]), "r"((a)[1]), "r"((a)[2]), "r"((a)[3]), "r"(b0), "r"(b1))
#define STSV2(addr, x, y) \
    asm volatile("st.shared.v2.b32 [%0], {%1,%2};" :: "r"((uint32_t)(addr)), "r"(x), "r"(y) : "memory")
#define STSV4(addr, x, y, z, w) \
    asm volatile("st.shared.v4.b32 [%0], {%1,%2,%3,%4};" :: "r"((uint32_t)(addr)), \
        "r"(x), "r"(y), "r"(z), "r"(w) : "memory")

// XOR swizzle for 64B-pitch rows (16B-granular; never add offsets after swizzling)
__device__ __forceinline__ uint32_t swz(uint32_t row, uint32_t colbyte) {
    return (row * 64 + colbyte) ^ ((row & 6) << 3);
}

__device__ __forceinline__ uint32_t packh2(float x, float y) {
    uint32_t r;
    asm("cvt.rn.f16x2.f32 %0, %1, %2;" : "=r"(r) : "f"(y), "f"(x));
    return r;
}
__device__ __forceinline__ void split2h(float x, float y, uint32_t& hi, uint32_t& lo) {
    uint32_t h = packh2(x, y);
    float hx, hy;
    asm("{ .reg .f16 a,b; mov.b32 {a,b}, %2; cvt.f32.f16 %0, a; cvt.f32.f16 %1, b; }"
        : "=f"(hx), "=f"(hy) : "r"(h));
    lo = packh2(x - hx, y - hy);
    hi = h;
}
__device__ __forceinline__ void split4h(float4 v, uint32_t& h01, uint32_t& h23,
                                        uint32_t& l01, uint32_t& l23) {
    split2h(v.x, v.y, h01, l01);
    split2h(v.z, v.w, h23, l23);
}

// ---------------- router + x pre-split ----------------
__global__ __launch_bounds__(128) void router_kernel(
    const float* __restrict__ x, const float* __restrict__ gw, float* __restrict__ logits, int T)
{
    int t = blockIdx.x, tid = threadIdx.x;
    float acc[NEXP];
#pragma unroll
    for (int e = 0; e < NEXP; e++) acc[e] = 0.f;
    const float* xr = x + (size_t)t * HDIM;
    for (int h = tid; h < HDIM; h += 128) {
        float xv = xr[h];
#pragma unroll
        for (int e = 0; e < NEXP; e++) acc[e] += xv * gw[e * HDIM + h];
    }
#pragma unroll
    for (int e = 0; e < NEXP; e++)
#pragma unroll
        for (int off = 16; off > 0; off >>= 1) acc[e] += __shfl_down_sync(0xffffffffu, acc[e], off);
    __shared__ float sred[4][NEXP];
    __shared__ float slog[NEXP];
    int warp = tid >> 5, lane = tid & 31;
    if (lane == 0)
#pragma unroll
        for (int e = 0; e < NEXP; e++) sred[warp][e] = acc[e];
    __syncthreads();
    if (tid < NEXP) {
        float v = sred[0][tid] + sred[1][tid] + sred[2][tid] + sred[3][tid];
        slog[tid] = v;
        logits[t * NEXP + tid] = v;
    }
    __syncthreads();

    for (int c = tid * 4; c < HDIM; c += 128 * 4) {
        float4 v = *(const float4*)(xr + c);
        uint32_t h01, h23, l01, l23;
        split4h(v, h01, h23, l01, l23);
        *(uint2*)(g_x_hi + (size_t)t * HDIM + c) = make_uint2(h01, h23);
        *(uint2*)(g_x_lo + (size_t)t * HDIM + c) = make_uint2(l01, l23);
    }

    if (tid == 0) {
        int i0 = 0; float v0 = slog[0];
#pragma unroll
        for (int e = 1; e < NEXP; e++) if (slog[e] > v0) { v0 = slog[e]; i0 = e; }
        int i1 = -1; float v1 = -INFINITY;
#pragma unroll
        for (int e = 0; e < NEXP; e++) { if (e == i0) continue; if (slog[e] > v1) { v1 = slog[e]; i1 = e; } }
        float e1 = expf(v1 - v0);
        float inv = 1.f / (1.f + e1);
        g_tok_e[t * 2 + 0] = i0; g_tok_w[t * 2 + 0] = inv;
        g_tok_e[t * 2 + 1] = i1; g_tok_w[t * 2 + 1] = e1 * inv;
        atomicAdd(&g_count[i0], 1);
        atomicAdd(&g_count[i1], 1);
    }
}

// offsets + dispatch merged, single block
__global__ __launch_bounds__(1024) void dispatch_kernel(int T)
{
    __shared__ int cur[NEXP];
    int tid = threadIdx.x;
    if (tid == 0) {
        int off = 0;
#pragma unroll
        for (int e = 0; e < NEXP; e++) { g_segstart[e] = off; cur[e] = off; off += g_count[e]; }
        g_segstart[NEXP] = off;
    }
    __syncthreads();
    for (int t = tid; t < T; t += 1024) {
#pragma unroll
        for (int s = 0; s < 2; s++) {
            int e = g_tok_e[t * 2 + s];
            int pos = atomicAdd(&cur[e], 1);
            g_pair_token[pos] = t;
            g_pair_w[pos]     = g_tok_w[t * 2 + s];
        }
    }
}

// =============== GEMM geometry: CTA 128x128, 8 warps (4m x 2n), warp 32x64, BK=64 ===============
// Stage 48KB: A_hi [0,16K) | A_lo [16K,32K) | B [32K,48K); sub s at +s*8192 per plane. 2 stages = 96KB.
#define STAGE 49152
#define GSMEM 98304

// -------- gu GEMM + fused SwiGLU: BN=128 = 64 gate cols (warp_n=0) + 64 up cols (warp_n=1) --------
__global__ __launch_bounds__(256, 1) void gu_gemm(
    const ushort_t* __restrict__ Ahi, const ushort_t* __restrict__ Alo,
    const float* __restrict__ B)
{
    int e = blockIdx.z;
    int seg0 = g_segstart[e];
    int cnt  = g_segstart[e + 1] - seg0;
    int m0 = blockIdx.x * 128;
    if (m0 >= cnt) return;
    int n0 = blockIdx.y * 64;                  // i-tile base (64 wide)

    extern __shared__ char smem[];
    uint32_t sbase = smem_u32(smem);

    int tid = threadIdx.x;
    int lane = tid & 31, wid = tid >> 5;
    int warp_m = wid >> 1;
    int warp_n = wid & 1;

    int row  = tid >> 1;
    int half = tid & 1;
    int mrow = m0 + row; if (mrow >= cnt) mrow = cnt - 1;
    int arow = g_pair_token[seg0 + mrow];
    const uint4* ahip = (const uint4*)(Ahi + (size_t)arow * HDIM + half * 16);
    const uint4* alop = (const uint4*)(Alo + (size_t)arow * HDIM + half * 16);
    int brow_log = (row < 64) ? (n0 + row) : (IDIM + n0 + row - 64);   // gate rows | up rows
    const float* bptr = B + (size_t)e * TWO_I * HDIM + (size_t)brow_log * HDIM + half * 16;

    uint32_t sts8[4], sts16[2];
#pragma unroll
    for (int j = 0; j < 4; j++) sts8[j] = swz((uint32_t)row, (uint32_t)(half * 32 + j * 8));
#pragma unroll
    for (int j = 0; j < 2; j++) sts16[j] = swz((uint32_t)row, (uint32_t)(half * 32 + j * 16));

    int a_r = lane & 15, a_k = lane >> 4;
    int b_n = (lane & 7) + ((lane & 16) ? 8 : 0);
    int b_k = (lane & 8) ? 1 : 0;
    uint32_t a_off[2][2], b_off[4][2];
#pragma unroll
    for (int mf = 0; mf < 2; mf++)
#pragma unroll
        for (int kx = 0; kx < 2; kx++)
            a_off[mf][kx] = swz((uint32_t)(warp_m * 32 + mf * 16 + a_r), (uint32_t)((kx * 2 + a_k) * 16));
#pragma unroll
    for (int nf = 0; nf < 4; nf++)
#pragma unroll
        for (int kx = 0; kx < 2; kx++)
            b_off[nf][kx] = swz((uint32_t)(warp_n * 64 + nf * 16 + b_n), (uint32_t)((kx * 2 + b_k) * 16));

    float acc[2][8][4];
#pragma unroll
    for (int mf = 0; mf < 2; mf++)
#pragma unroll
        for (int j = 0; j < 8; j++)
#pragma unroll
            for (int q = 0; q < 4; q++) acc[mf][j][q] = 0.f;

    const int NCH = HDIM / 64;
    float4 pb[8];
    uint4  pah[4], pal[4];

    auto ldg_chunk = [&](int c) {
#pragma unroll
        for (int s = 0; s < 2; s++) {
#pragma unroll
            for (int j = 0; j < 2; j++) {
                pah[s * 2 + j] = ahip[c * 8 + s * 4 + j];
                pal[s * 2 + j] = alop[c * 8 + s * 4 + j];
            }
#pragma unroll
            for (int j = 0; j < 4; j++)
                pb[s * 4 + j] = ((const float4*)bptr)[c * 16 + s * 8 + j];
        }
    };
    auto sts_chunk = [&](uint32_t sb) {
#pragma unroll
        for (int s = 0; s < 2; s++) {
            uint32_t subA  = sb + s * 8192;
            uint32_t subAl = sb + 16384 + s * 8192;
            uint32_t subB  = sb + 32768 + s * 8192;
#pragma unroll
            for (int j = 0; j < 2; j++) {
                uint4 h = pah[s * 2 + j], l = pal[s * 2 + j];
                STSV4(subA  + sts16[j], h.x, h.y, h.z, h.w);
                STSV4(subAl + sts16[j], l.x, l.y, l.z, l.w);
            }
#pragma unroll
            for (int j = 0; j < 4; j++) {
                float4 v = pb[s * 4 + j];
                STSV2(subB + sts8[j], packh2(v.x, v.y), packh2(v.z, v.w));
            }
        }
    };

    ldg_chunk(0);
    sts_chunk(sbase);
    ldg_chunk(1);
    __syncthreads();

#pragma unroll 2
    for (int ch = 0; ch < NCH; ch++) {
        uint32_t sb  = sbase + (ch & 1) * STAGE;
        uint32_t sbn = sbase + ((ch + 1) & 1) * STAGE;
        if (ch + 1 < NCH) sts_chunk(sbn);
#pragma unroll
        for (int kk = 0; kk < 4; kk++) {
            int sub = kk >> 1, kx = kk & 1;
            uint32_t baseA  = sb + sub * 8192;
            uint32_t baseAl = sb + 16384 + sub * 8192;
            uint32_t baseB  = sb + 32768 + sub * 8192;
            uint32_t ahf[2][4], alf[2][4];
#pragma unroll
            for (int mf = 0; mf < 2; mf++) {
                LDMX4(ahf[mf], baseA  + a_off[mf][kx]);
                LDMX4(alf[mf], baseAl + a_off[mf][kx]);
            }
#pragma unroll
            for (int nf = 0; nf < 4; nf++) {
                uint32_t bf[4];
                LDMX4(bf, baseB + b_off[nf][kx]);
#pragma unroll
                for (int mf = 0; mf < 2; mf++)
#pragma unroll
                    for (int jj = 0; jj < 2; jj++) {
                        int j = nf * 2 + jj;
                        MMA(acc[mf][j], ahf[mf], bf[jj * 2], bf[jj * 2 + 1]);
                        MMA(acc[mf][j], alf[mf], bf[jj * 2], bf[jj * 2 + 1]);
                    }
            }
        }
        if (ch + 2 < NCH) ldg_chunk(ch + 2);
        __syncthreads();
    }

    // -------- fused SwiGLU epilogue --------
    float* gbuf = (float*)smem;                // [128][68] fp32 = 34.8KB (stage smem reused)
    int erow = lane >> 2;
    int ecol = (lane & 3) * 2;

    if (warp_n == 0) {                         // gate warps stage g (cols 0..63)
#pragma unroll
        for (int mf = 0; mf < 2; mf++) {
            int r0 = warp_m * 32 + mf * 16 + erow;
#pragma unroll
            for (int j = 0; j < 8; j++) {
                int col = j * 8 + ecol;
                gbuf[r0 * 68 + col]           = acc[mf][j][0];
                gbuf[r0 * 68 + col + 1]       = acc[mf][j][1];
                gbuf[(r0 + 8) * 68 + col]     = acc[mf][j][2];
                gbuf[(r0 + 8) * 68 + col + 1] = acc[mf][j][3];
            }
        }
    }
    __syncthreads();
    if (warp_n == 1) {                         // up warps: h = silu(g)*u, split, store
#pragma unroll
        for (int mf = 0; mf < 2; mf++) {
            int r0 = warp_m * 32 + mf * 16 + erow;
#pragma unroll
            for (int j = 0; j < 8; j++) {
                int ucol = j * 8 + ecol;       // 0..63
#pragma unroll
                for (int rr = 0; rr < 2; rr++) {
                    int r = r0 + rr * 8;
                    if (m0 + r >= cnt) continue;
                    float g0 = gbuf[r * 68 + ucol];
                    float g1 = gbuf[r * 68 + ucol + 1];
                    float u0 = acc[mf][j][rr * 2 + 0];
                    float u1 = acc[mf][j][rr * 2 + 1];
                    float h0 = u0 * g0 / (1.f + expf(-g0));
                    float h1 = u1 * g1 / (1.f + expf(-g1));
                    uint32_t hi, lo;
                    split2h(h0, h1, hi, lo);
                    size_t off = (size_t)(seg0 + m0 + r) * IDIM + n0 + ucol;
                    *(uint32_t*)(g_h_hi + off) = hi;
                    *(uint32_t*)(g_h_lo + off) = lo;
                }
            }
        }
    }
}

// -------- down GEMM (round-15 verbatim): A = h planes, weighted atomic scatter into out --------
__global__ __launch_bounds__(256, 1) void down_gemm(
    const ushort_t* __restrict__ Ahi, const ushort_t* __restrict__ Alo,
    const float* __restrict__ B, float* __restrict__ C)
{
    int e = blockIdx.z;
    int seg0 = g_segstart[e];
    int cnt  = g_segstart[e + 1] - seg0;
    int m0 = blockIdx.x * 128;
    if (m0 >= cnt) return;
    int n0 = blockIdx.y * 128;

    extern __shared__ char smem[];
    uint32_t sbase = smem_u32(smem);

    int tid = threadIdx.x;
    int lane = tid & 31, wid = tid >> 5;
    int warp_m = wid >> 1;
    int warp_n = wid & 1;

    int row  = tid >> 1;
    int half = tid & 1;
    int mrow = m0 + row; if (mrow >= cnt) mrow = cnt - 1;
    const uint4* ahip = (const uint4*)(Ahi + (size_t)(seg0 + mrow) * IDIM + half * 16);
    const uint4* alop = (const uint4*)(Alo + (size_t)(seg0 + mrow) * IDIM + half * 16);
    const float* bptr = B + (size_t)e * HDIM * IDIM + (size_t)(n0 + row) * IDIM + half * 16;

    uint32_t sts8[4], sts16[2];
#pragma unroll
    for (int j = 0; j < 4; j++) sts8[j] = swz((uint32_t)row, (uint32_t)(half * 32 + j * 8));
#pragma unroll
    for (int j = 0; j < 2; j++) sts16[j] = swz((uint32_t)row, (uint32_t)(half * 32 + j * 16));

    int a_r = lane & 15, a_k = lane >> 4;
    int b_n = (lane & 7) + ((lane & 16) ? 8 : 0);
    int b_k = (lane & 8) ? 1 : 0;
    uint32_t a_off[2][2], b_off[4][2];
#pragma unroll
    for (int mf = 0; mf < 2; mf++)
#pragma unroll
        for (int kx = 0; kx < 2; kx++)
            a_off[mf][kx] = swz((uint32_t)(warp_m * 32 + mf * 16 + a_r), (uint32_t)((kx * 2 + a_k) * 16));
#pragma unroll
    for (int nf = 0; nf < 4; nf++)
#pragma unroll
        for (int kx = 0; kx < 2; kx++)
            b_off[nf][kx] = swz((uint32_t)(warp_n * 64 + nf * 16 + b_n), (uint32_t)((kx * 2 + b_k) * 16));

    float acc[2][8][4];
#pragma unroll
    for (int mf = 0; mf < 2; mf++)
#pragma unroll
        for (int j = 0; j < 8; j++)
#pragma unroll
            for (int q = 0; q < 4; q++) acc[mf][j][q] = 0.f;

    const int NCH = IDIM / 64;
    float4 pb[8];
    uint4  pah[4], pal[4];

    auto ldg_chunk = [&](int c) {
#pragma unroll
        for (int s = 0; s < 2; s++) {
#pragma unroll
            for (int j = 0; j < 2; j++) {
                pah[s * 2 + j] = ahip[c * 8 + s * 4 + j];
                pal[s * 2 + j] = alop[c * 8 + s * 4 + j];
            }
#pragma unroll
            for (int j = 0; j < 4; j++)
                pb[s * 4 + j] = ((const float4*)bptr)[c * 16 + s * 8 + j];
        }
    };
    auto sts_chunk = [&](uint32_t sb) {
#pragma unroll
        for (int s = 0; s < 2; s++) {
            uint32_t subA  = sb + s * 8192;
            uint32_t subAl = sb + 16384 + s * 8192;
            uint32_t subB  = sb + 32768 + s * 8192;
#pragma unroll
            for (int j = 0; j < 2; j++) {
                uint4 h = pah[s * 2 + j], l = pal[s * 2 + j];
                STSV4(subA  + sts16[j], h.x, h.y, h.z, h.w);
                STSV4(subAl + sts16[j], l.x, l.y, l.z, l.w);
            }
#pragma unroll
            for (int j = 0; j < 4; j++) {
                float4 v = pb[s * 4 + j];
                STSV2(subB + sts8[j], packh2(v.x, v.y), packh2(v.z, v.w));
            }
        }
    };

    ldg_chunk(0);
    sts_chunk(sbase);
    ldg_chunk(1);
    __syncthreads();

#pragma unroll 2
    for (int ch = 0; ch < NCH; ch++) {
        uint32_t sb  = sbase + (ch & 1) * STAGE;
        uint32_t sbn = sbase + ((ch + 1) & 1) * STAGE;
        if (ch + 1 < NCH) sts_chunk(sbn);
#pragma unroll
        for (int kk = 0; kk < 4; kk++) {
            int sub = kk >> 1, kx = kk & 1;
            uint32_t baseA  = sb + sub * 8192;
            uint32_t baseAl = sb + 16384 + sub * 8192;
            uint32_t baseB  = sb + 32768 + sub * 8192;
            uint32_t ahf[2][4], alf[2][4];
#pragma unroll
            for (int mf = 0; mf < 2; mf++) {
                LDMX4(ahf[mf], baseA  + a_off[mf][kx]);
                LDMX4(alf[mf], baseAl + a_off[mf][kx]);
            }
#pragma unroll
            for (int nf = 0; nf < 4; nf++) {
                uint32_t bf[4];
                LDMX4(bf, baseB + b_off[nf][kx]);
#pragma unroll
                for (int mf = 0; mf < 2; mf++)
#pragma unroll
                    for (int jj = 0; jj < 2; jj++) {
                        int j = nf * 2 + jj;
                        MMA(acc[mf][j], ahf[mf], bf[jj * 2], bf[jj * 2 + 1]);
                        MMA(acc[mf][j], alf[mf], bf[jj * 2], bf[jj * 2 + 1]);
                    }
            }
        }
        if (ch + 2 < NCH) ldg_chunk(ch + 2);
        __syncthreads();
    }

    int erow = lane >> 2;
    int ecol = (lane & 3) * 2;
#pragma unroll
    for (int mf = 0; mf < 2; mf++) {
        int mloc0 = m0 + warp_m * 32 + mf * 16 + erow;
        int mloc1 = mloc0 + 8;
        int   t0 = 0, t1 = 0; float w0 = 0.f, w1 = 0.f;
        if (mloc0 < cnt) { t0 = g_pair_token[seg0 + mloc0]; w0 = g_pair_w[seg0 + mloc0]; }
        if (mloc1 < cnt) { t1 = g_pair_token[seg0 + mloc1]; w1 = g_pair_w[seg0 + mloc1]; }
#pragma unroll
        for (int j = 0; j < 8; j++) {
            int nglob = n0 + warp_n * 64 + j * 8 + ecol;
            if (mloc0 < cnt) {
                atomicAdd(C + (size_t)t0 * HDIM + nglob,     w0 * acc[mf][j][0]);
                atomicAdd(C + (size_t)t0 * HDIM + nglob + 1, w0 * acc[mf][j][1]);
            }
            if (mloc1 < cnt) {
                atomicAdd(C + (size_t)t1 * HDIM + nglob,     w1 * acc[mf][j][2]);
                atomicAdd(C + (size_t)t1 * HDIM + nglob + 1, w1 * acc[mf][j][3]);
            }
        }
    }
}

// ---------------- launch ----------------
extern "C" void kernel_launch(void* const* d_in, const int* in_sizes, int n_in,
                              void* d_out, int out_size)
{
    const float* x   = (const float*)d_in[0];
    const float* gw  = (const float*)d_in[1];
    const float* gup = (const float*)d_in[2];
    const float* dw  = (const float*)d_in[3];
    float* out = (float*)d_out;

    int T = in_sizes[0] / HDIM;
    size_t main_sz = (size_t)T * HDIM;

    float* logits;
    if ((size_t)out_size >= main_sz + (size_t)T * NEXP) logits = out + main_sz;
    else cudaGetSymbolAddress((void**)&logits, g_logits_fallback);

    cudaFuncSetAttribute(gu_gemm,   cudaFuncAttributeMaxDynamicSharedMemorySize, GSMEM);
    cudaFuncSetAttribute(down_gemm, cudaFuncAttributeMaxDynamicSharedMemorySize, GSMEM);

    int* d_count; cudaGetSymbolAddress((void**)&d_count, g_count);
    cudaMemsetAsync(d_count, 0, NEXP * sizeof(int), 0);
    cudaMemsetAsync(out, 0, main_sz * sizeof(float), 0);

    router_kernel<<<T, 128>>>(x, gw, logits, T);
    dispatch_kernel<<<1, 1024>>>(T);

    int mtiles = (T + 127) / 128;
    ushort_t *d_xh, *d_xl, *d_hh, *d_hl;
    cudaGetSymbolAddress((void**)&d_xh, g_x_hi);
    cudaGetSymbolAddress((void**)&d_xl, g_x_lo);
    cudaGetSymbolAddress((void**)&d_hh, g_h_hi);
    cudaGetSymbolAddress((void**)&d_hl, g_h_lo);

    dim3 gu_grid(mtiles, IDIM / 64, NEXP);
    gu_gemm<<<gu_grid, 256, GSMEM>>>(d_xh, d_xl, gup);

    dim3 dn_grid(mtiles, HDIM / 128, NEXP);
    down_gemm<<<dn_grid, 256, GSMEM>>>(d_hh, d_hl, dw, out);
}

// round 17
// speedup vs baseline: 1.0934x; 1.0934x over previous
#include <cuda_runtime.h>
#include <cuda_fp16.h>
#include <math.h>
#include <stdint.h>

#define HDIM 2048
#define NEXP 16
#define IDIM 768
#define TWO_I 1536
#define TMAX 2048
#define PMAX (TMAX*2)

typedef unsigned short ushort_t;

// ---------------- device scratch ----------------
__device__ int   g_count[NEXP];
__device__ int   g_segstart[NEXP + 1];
__device__ int   g_tok_e[TMAX * 2];
__device__ float g_tok_w[TMAX * 2];
__device__ int   g_pair_token[PMAX];
__device__ float g_pair_w[PMAX];
__device__ __align__(16) ushort_t g_x_hi[(size_t)TMAX * HDIM];
__device__ __align__(16) ushort_t g_x_lo[(size_t)TMAX * HDIM];
__device__ __align__(16) float    g_gu[(size_t)PMAX * TWO_I];
__device__ __align__(16) ushort_t g_h16[(size_t)PMAX * IDIM];    // h as single f16 plane
__device__ float g_logits_fallback[TMAX * NEXP];

// ---------------- portable PTX helpers ----------------
__device__ __forceinline__ uint32_t smem_u32(const void* p) {
    uint32_t a;
    asm("{ .reg .u64 t; cvta.to.shared.u64 t, %1; cvt.u32.u64 %0, t; }" : "=r"(a) : "l"(p));
    return a;
}
#define LDMX4(r, addr) \
    asm volatile("ldmatrix.sync.aligned.m8n8.x4.shared.b16 {%0,%1,%2,%3}, [%4];" \
        : "=r"((r)[0]), "=r"((r)[1]), "=r"((r)[2]), "=r"((r)[3]) : "r"(addr))
#define MMA(acc, a, b0, b1) \
    asm volatile("mma.sync.aligned.m16n8k16.row.col.f32.f16.f16.f32 " \
        "{%0,%1,%2,%3}, {%4,%5,%6,%7}, {%8,%9}, {%0,%1,%2,%3};" \
        : "+f"((acc)[0]), "+f"((acc)[1]), "+f"((acc)[2]), "+f"((acc)[3]) \
        : "r"((a)[0]), "r"((a)[1]), "r"((a)[2]), "r"((a)[3]), "r"(b0), "r"(b1))
#define STSV2(addr, x, y) \
    asm volatile("st.shared.v2.b32 [%0], {%1,%2};" :: "r"((uint32_t)(addr)), "r"(x), "r"(y) : "memory")
#define STSV4(addr, x, y, z, w) \
    asm volatile("st.shared.v4.b32 [%0], {%1,%2,%3,%4};" :: "r"((uint32_t)(addr)), \
        "r"(x), "r"(y), "r"(z), "r"(w) : "memory")

// XOR swizzle for 64B-pitch rows (16B-granular; never add offsets after swizzling)
__device__ __forceinline__ uint32_t swz(uint32_t row, uint32_t colbyte) {
    return (row * 64 + colbyte) ^ ((row & 6) << 3);
}

__device__ __forceinline__ uint32_t packh2(float x, float y) {
    uint32_t r;
    asm("cvt.rn.f16x2.f32 %0, %1, %2;" : "=r"(r) : "f"(y), "f"(x));
    return r;
}
__device__ __forceinline__ void split2h(float x, float y, uint32_t& hi, uint32_t& lo) {
    uint32_t h = packh2(x, y);
    float hx, hy;
    asm("{ .reg .f16 a,b; mov.b32 {a,b}, %2; cvt.f32.f16 %0, a; cvt.f32.f16 %1, b; }"
        : "=f"(hx), "=f"(hy) : "r"(h));
    lo = packh2(x - hx, y - hy);
    hi = h;
}
__device__ __forceinline__ void split4h(float4 v, uint32_t& h01, uint32_t& h23,
                                        uint32_t& l01, uint32_t& l23) {
    split2h(v.x, v.y, h01, l01);
    split2h(v.z, v.w, h23, l23);
}

// ---------------- router + x pre-split ----------------
__global__ __launch_bounds__(128) void router_kernel(
    const float* __restrict__ x, const float* __restrict__ gw, float* __restrict__ logits, int T)
{
    int t = blockIdx.x, tid = threadIdx.x;
    float acc[NEXP];
#pragma unroll
    for (int e = 0; e < NEXP; e++) acc[e] = 0.f;
    const float* xr = x + (size_t)t * HDIM;
    for (int h = tid; h < HDIM; h += 128) {
        float xv = xr[h];
#pragma unroll
        for (int e = 0; e < NEXP; e++) acc[e] += xv * gw[e * HDIM + h];
    }
#pragma unroll
    for (int e = 0; e < NEXP; e++)
#pragma unroll
        for (int off = 16; off > 0; off >>= 1) acc[e] += __shfl_down_sync(0xffffffffu, acc[e], off);
    __shared__ float sred[4][NEXP];
    __shared__ float slog[NEXP];
    int warp = tid >> 5, lane = tid & 31;
    if (lane == 0)
#pragma unroll
        for (int e = 0; e < NEXP; e++) sred[warp][e] = acc[e];
    __syncthreads();
    if (tid < NEXP) {
        float v = sred[0][tid] + sred[1][tid] + sred[2][tid] + sred[3][tid];
        slog[tid] = v;
        logits[t * NEXP + tid] = v;
    }
    __syncthreads();

    for (int c = tid * 4; c < HDIM; c += 128 * 4) {
        float4 v = *(const float4*)(xr + c);
        uint32_t h01, h23, l01, l23;
        split4h(v, h01, h23, l01, l23);
        *(uint2*)(g_x_hi + (size_t)t * HDIM + c) = make_uint2(h01, h23);
        *(uint2*)(g_x_lo + (size_t)t * HDIM + c) = make_uint2(l01, l23);
    }

    if (tid == 0) {
        int i0 = 0; float v0 = slog[0];
#pragma unroll
        for (int e = 1; e < NEXP; e++) if (slog[e] > v0) { v0 = slog[e]; i0 = e; }
        int i1 = -1; float v1 = -INFINITY;
#pragma unroll
        for (int e = 0; e < NEXP; e++) { if (e == i0) continue; if (slog[e] > v1) { v1 = slog[e]; i1 = e; } }
        float e1 = expf(v1 - v0);
        float inv = 1.f / (1.f + e1);
        g_tok_e[t * 2 + 0] = i0; g_tok_w[t * 2 + 0] = inv;
        g_tok_e[t * 2 + 1] = i1; g_tok_w[t * 2 + 1] = e1 * inv;
        atomicAdd(&g_count[i0], 1);
        atomicAdd(&g_count[i1], 1);
    }
}

// offsets + dispatch merged, single block
__global__ __launch_bounds__(1024) void dispatch_kernel(int T)
{
    __shared__ int cur[NEXP];
    int tid = threadIdx.x;
    if (tid == 0) {
        int off = 0;
#pragma unroll
        for (int e = 0; e < NEXP; e++) { g_segstart[e] = off; cur[e] = off; off += g_count[e]; }
        g_segstart[NEXP] = off;
    }
    __syncthreads();
    for (int t = tid; t < T; t += 1024) {
#pragma unroll
        for (int s = 0; s < 2; s++) {
            int e = g_tok_e[t * 2 + s];
            int pos = atomicAdd(&cur[e], 1);
            g_pair_token[pos] = t;
            g_pair_w[pos]     = g_tok_w[t * 2 + s];
        }
    }
}

// =============== gu GEMM (round-15 winner): CTA 128x128, 4m x 2n warps, warp 32x64, BK=64 ===============
// Stage 48KB: A_hi [0,16K) | A_lo [16K,32K) | B [32K,48K); sub s at +s*8192 per plane. 2 stages = 96KB.
#define STAGE_GU 49152
#define GSMEM_GU 98304

__global__ __launch_bounds__(256, 1) void gu_gemm(
    const ushort_t* __restrict__ Ahi, const ushort_t* __restrict__ Alo,
    const float* __restrict__ B, float* __restrict__ C)
{
    int e = blockIdx.z;
    int seg0 = g_segstart[e];
    int cnt  = g_segstart[e + 1] - seg0;
    int m0 = blockIdx.x * 128;
    if (m0 >= cnt) return;
    int n0 = blockIdx.y * 128;

    extern __shared__ char smem[];
    uint32_t sbase = smem_u32(smem);

    int tid = threadIdx.x;
    int lane = tid & 31, wid = tid >> 5;
    int warp_m = wid >> 1;
    int warp_n = wid & 1;

    int row  = tid >> 1;
    int half = tid & 1;
    int mrow = m0 + row; if (mrow >= cnt) mrow = cnt - 1;
    int arow = g_pair_token[seg0 + mrow];
    const uint4* ahip = (const uint4*)(Ahi + (size_t)arow * HDIM + half * 16);
    const uint4* alop = (const uint4*)(Alo + (size_t)arow * HDIM + half * 16);
    const float* bptr = B + (size_t)e * TWO_I * HDIM + (size_t)(n0 + row) * HDIM + half * 16;

    uint32_t sts8[4], sts16[2];
#pragma unroll
    for (int j = 0; j < 4; j++) sts8[j] = swz((uint32_t)row, (uint32_t)(half * 32 + j * 8));
#pragma unroll
    for (int j = 0; j < 2; j++) sts16[j] = swz((uint32_t)row, (uint32_t)(half * 32 + j * 16));

    int a_r = lane & 15, a_k = lane >> 4;
    int b_n = (lane & 7) + ((lane & 16) ? 8 : 0);
    int b_k = (lane & 8) ? 1 : 0;
    uint32_t a_off[2][2], b_off[4][2];
#pragma unroll
    for (int mf = 0; mf < 2; mf++)
#pragma unroll
        for (int kx = 0; kx < 2; kx++)
            a_off[mf][kx] = swz((uint32_t)(warp_m * 32 + mf * 16 + a_r), (uint32_t)((kx * 2 + a_k) * 16));
#pragma unroll
    for (int nf = 0; nf < 4; nf++)
#pragma unroll
        for (int kx = 0; kx < 2; kx++)
            b_off[nf][kx] = swz((uint32_t)(warp_n * 64 + nf * 16 + b_n), (uint32_t)((kx * 2 + b_k) * 16));

    float acc[2][8][4];
#pragma unroll
    for (int mf = 0; mf < 2; mf++)
#pragma unroll
        for (int j = 0; j < 8; j++)
#pragma unroll
            for (int q = 0; q < 4; q++) acc[mf][j][q] = 0.f;

    const int NCH = HDIM / 64;
    float4 pb[8];
    uint4  pah[4], pal[4];

    auto ldg_chunk = [&](int c) {
#pragma unroll
        for (int s = 0; s < 2; s++) {
#pragma unroll
            for (int j = 0; j < 2; j++) {
                pah[s * 2 + j] = ahip[c * 8 + s * 4 + j];
                pal[s * 2 + j] = alop[c * 8 + s * 4 + j];
            }
#pragma unroll
            for (int j = 0; j < 4; j++)
                pb[s * 4 + j] = ((const float4*)bptr)[c * 16 + s * 8 + j];
        }
    };
    auto sts_chunk = [&](uint32_t sb) {
#pragma unroll
        for (int s = 0; s < 2; s++) {
            uint32_t subA  = sb + s * 8192;
            uint32_t subAl = sb + 16384 + s * 8192;
            uint32_t subB  = sb + 32768 + s * 8192;
#pragma unroll
            for (int j = 0; j < 2; j++) {
                uint4 h = pah[s * 2 + j], l = pal[s * 2 + j];
                STSV4(subA  + sts16[j], h.x, h.y, h.z, h.w);
                STSV4(subAl + sts16[j], l.x, l.y, l.z, l.w);
            }
#pragma unroll
            for (int j = 0; j < 4; j++) {
                float4 v = pb[s * 4 + j];
                STSV2(subB + sts8[j], packh2(v.x, v.y), packh2(v.z, v.w));
            }
        }
    };

    ldg_chunk(0);
    sts_chunk(sbase);
    ldg_chunk(1);
    __syncthreads();

#pragma unroll 2
    for (int ch = 0; ch < NCH; ch++) {
        uint32_t sb  = sbase + (ch & 1) * STAGE_GU;
        uint32_t sbn = sbase + ((ch + 1) & 1) * STAGE_GU;
        if (ch + 1 < NCH) sts_chunk(sbn);
#pragma unroll
        for (int kk = 0; kk < 4; kk++) {
            int sub = kk >> 1, kx = kk & 1;
            uint32_t baseA  = sb + sub * 8192;
            uint32_t baseAl = sb + 16384 + sub * 8192;
            uint32_t baseB  = sb + 32768 + sub * 8192;
            uint32_t ahf[2][4], alf[2][4];
#pragma unroll
            for (int mf = 0; mf < 2; mf++) {
                LDMX4(ahf[mf], baseA  + a_off[mf][kx]);
                LDMX4(alf[mf], baseAl + a_off[mf][kx]);
            }
#pragma unroll
            for (int nf = 0; nf < 4; nf++) {
                uint32_t bf[4];
                LDMX4(bf, baseB + b_off[nf][kx]);
#pragma unroll
                for (int mf = 0; mf < 2; mf++)
#pragma unroll
                    for (int jj = 0; jj < 2; jj++) {
                        int j = nf * 2 + jj;
                        MMA(acc[mf][j], ahf[mf], bf[jj * 2], bf[jj * 2 + 1]);
                        MMA(acc[mf][j], alf[mf], bf[jj * 2], bf[jj * 2 + 1]);
                    }
            }
        }
        if (ch + 2 < NCH) ldg_chunk(ch + 2);
        __syncthreads();
    }

    int erow = lane >> 2;
    int ecol = (lane & 3) * 2;
#pragma unroll
    for (int mf = 0; mf < 2; mf++) {
        int mloc0 = m0 + warp_m * 32 + mf * 16 + erow;
        int mloc1 = mloc0 + 8;
#pragma unroll
        for (int j = 0; j < 8; j++) {
            int nglob = n0 + warp_n * 64 + j * 8 + ecol;
            if (mloc0 < cnt)
                *(float2*)(C + (size_t)(seg0 + mloc0) * TWO_I + nglob) = make_float2(acc[mf][j][0], acc[mf][j][1]);
            if (mloc1 < cnt)
                *(float2*)(C + (size_t)(seg0 + mloc1) * TWO_I + nglob) = make_float2(acc[mf][j][2], acc[mf][j][3]);
        }
    }
}

// =============== down GEMM: SINGLE f16 A plane, CTA 128x128, BK=64 ===============
// Stage 32KB: A [0,16K) | B [16K,32K); sub s at +s*8192 per plane. 2 stages = 64KB.
#define STAGE_DN 32768
#define GSMEM_DN 65536

__global__ __launch_bounds__(256, 1) void down_gemm(
    const ushort_t* __restrict__ A16,
    const float* __restrict__ B, float* __restrict__ C)
{
    int e = blockIdx.z;
    int seg0 = g_segstart[e];
    int cnt  = g_segstart[e + 1] - seg0;
    int m0 = blockIdx.x * 128;
    if (m0 >= cnt) return;
    int n0 = blockIdx.y * 128;

    extern __shared__ char smem[];
    uint32_t sbase = smem_u32(smem);

    int tid = threadIdx.x;
    int lane = tid & 31, wid = tid >> 5;
    int warp_m = wid >> 1;
    int warp_n = wid & 1;

    int row  = tid >> 1;
    int half = tid & 1;
    int mrow = m0 + row; if (mrow >= cnt) mrow = cnt - 1;
    const uint4* ap = (const uint4*)(A16 + (size_t)(seg0 + mrow) * IDIM + half * 16);
    const float* bptr = B + (size_t)e * HDIM * IDIM + (size_t)(n0 + row) * IDIM + half * 16;

    uint32_t sts8[4], sts16[2];
#pragma unroll
    for (int j = 0; j < 4; j++) sts8[j] = swz((uint32_t)row, (uint32_t)(half * 32 + j * 8));
#pragma unroll
    for (int j = 0; j < 2; j++) sts16[j] = swz((uint32_t)row, (uint32_t)(half * 32 + j * 16));

    int a_r = lane & 15, a_k = lane >> 4;
    int b_n = (lane & 7) + ((lane & 16) ? 8 : 0);
    int b_k = (lane & 8) ? 1 : 0;
    uint32_t a_off[2][2], b_off[4][2];
#pragma unroll
    for (int mf = 0; mf < 2; mf++)
#pragma unroll
        for (int kx = 0; kx < 2; kx++)
            a_off[mf][kx] = swz((uint32_t)(warp_m * 32 + mf * 16 + a_r), (uint32_t)((kx * 2 + a_k) * 16));
#pragma unroll
    for (int nf = 0; nf < 4; nf++)
#pragma unroll
        for (int kx = 0; kx < 2; kx++)
            b_off[nf][kx] = swz((uint32_t)(warp_n * 64 + nf * 16 + b_n), (uint32_t)((kx * 2 + b_k) * 16));

    float acc[2][8][4];
#pragma unroll
    for (int mf = 0; mf < 2; mf++)
#pragma unroll
        for (int j = 0; j < 8; j++)
#pragma unroll
            for (int q = 0; q < 4; q++) acc[mf][j][q] = 0.f;

    const int NCH = IDIM / 64;
    float4 pb[8];
    uint4  pa[4];

    auto ldg_chunk = [&](int c) {
#pragma unroll
        for (int s = 0; s < 2; s++) {
#pragma unroll
            for (int j = 0; j < 2; j++)
                pa[s * 2 + j] = ap[c * 8 + s * 4 + j];
#pragma unroll
            for (int j = 0; j < 4; j++)
                pb[s * 4 + j] = ((const float4*)bptr)[c * 16 + s * 8 + j];
        }
    };
    auto sts_chunk = [&](uint32_t sb) {
#pragma unroll
        for (int s = 0; s < 2; s++) {
            uint32_t subA = sb + s * 8192;
            uint32_t subB = sb + 16384 + s * 8192;
#pragma unroll
            for (int j = 0; j < 2; j++) {
                uint4 h = pa[s * 2 + j];
                STSV4(subA + sts16[j], h.x, h.y, h.z, h.w);
            }
#pragma unroll
            for (int j = 0; j < 4; j++) {
                float4 v = pb[s * 4 + j];
                STSV2(subB + sts8[j], packh2(v.x, v.y), packh2(v.z, v.w));
            }
        }
    };

    ldg_chunk(0);
    sts_chunk(sbase);
    ldg_chunk(1);
    __syncthreads();

#pragma unroll 2
    for (int ch = 0; ch < NCH; ch++) {
        uint32_t sb  = sbase + (ch & 1) * STAGE_DN;
        uint32_t sbn = sbase + ((ch + 1) & 1) * STAGE_DN;
        if (ch + 1 < NCH) sts_chunk(sbn);
#pragma unroll
        for (int kk = 0; kk < 4; kk++) {
            int sub = kk >> 1, kx = kk & 1;
            uint32_t baseA = sb + sub * 8192;
            uint32_t baseB = sb + 16384 + sub * 8192;
            uint32_t af[2][4];
#pragma unroll
            for (int mf = 0; mf < 2; mf++)
                LDMX4(af[mf], baseA + a_off[mf][kx]);
#pragma unroll
            for (int nf = 0; nf < 4; nf++) {
                uint32_t bf[4];
                LDMX4(bf, baseB + b_off[nf][kx]);
#pragma unroll
                for (int mf = 0; mf < 2; mf++)
#pragma unroll
                    for (int jj = 0; jj < 2; jj++) {
                        int j = nf * 2 + jj;
                        MMA(acc[mf][j], af[mf], bf[jj * 2], bf[jj * 2 + 1]);
                    }
            }
        }
        if (ch + 2 < NCH) ldg_chunk(ch + 2);
        __syncthreads();
    }

    int erow = lane >> 2;
    int ecol = (lane & 3) * 2;
#pragma unroll
    for (int mf = 0; mf < 2; mf++) {
        int mloc0 = m0 + warp_m * 32 + mf * 16 + erow;
        int mloc1 = mloc0 + 8;
        int   t0 = 0, t1 = 0; float w0 = 0.f, w1 = 0.f;
        if (mloc0 < cnt) { t0 = g_pair_token[seg0 + mloc0]; w0 = g_pair_w[seg0 + mloc0]; }
        if (mloc1 < cnt) { t1 = g_pair_token[seg0 + mloc1]; w1 = g_pair_w[seg0 + mloc1]; }
#pragma unroll
        for (int j = 0; j < 8; j++) {
            int nglob = n0 + warp_n * 64 + j * 8 + ecol;
            if (mloc0 < cnt) {
                atomicAdd(C + (size_t)t0 * HDIM + nglob,     w0 * acc[mf][j][0]);
                atomicAdd(C + (size_t)t0 * HDIM + nglob + 1, w0 * acc[mf][j][1]);
            }
            if (mloc1 < cnt) {
                atomicAdd(C + (size_t)t1 * HDIM + nglob,     w1 * acc[mf][j][2]);
                atomicAdd(C + (size_t)t1 * HDIM + nglob + 1, w1 * acc[mf][j][3]);
            }
        }
    }
}

// ---------------- SwiGLU elementwise: fp32 gu -> single f16 h ----------------
__global__ __launch_bounds__(256) void swiglu_kernel(int npairs)
{
    int idx = blockIdx.x * blockDim.x + threadIdx.x;
    if (idx >= npairs * (IDIM / 4)) return;
    int p = idx / (IDIM / 4);
    int c = idx % (IDIM / 4);
    float4 g4 = ((const float4*)g_gu)[(size_t)p * (TWO_I / 4) + c];
    float4 u4 = ((const float4*)g_gu)[(size_t)p * (TWO_I / 4) + (IDIM / 4) + c];
    float4 h;
    h.x = u4.x * g4.x / (1.f + expf(-g4.x));
    h.y = u4.y * g4.y / (1.f + expf(-g4.y));
    h.z = u4.z * g4.z / (1.f + expf(-g4.z));
    h.w = u4.w * g4.w / (1.f + expf(-g4.w));
    uint32_t h01 = packh2(h.x, h.y);
    uint32_t h23 = packh2(h.z, h.w);
    ((uint2*)g_h16)[idx] = make_uint2(h01, h23);
}

// ---------------- launch ----------------
extern "C" void kernel_launch(void* const* d_in, const int* in_sizes, int n_in,
                              void* d_out, int out_size)
{
    const float* x   = (const float*)d_in[0];
    const float* gw  = (const float*)d_in[1];
    const float* gup = (const float*)d_in[2];
    const float* dw  = (const float*)d_in[3];
    float* out = (float*)d_out;

    int T = in_sizes[0] / HDIM;
    size_t main_sz = (size_t)T * HDIM;

    float* logits;
    if ((size_t)out_size >= main_sz + (size_t)T * NEXP) logits = out + main_sz;
    else cudaGetSymbolAddress((void**)&logits, g_logits_fallback);

    cudaFuncSetAttribute(gu_gemm,   cudaFuncAttributeMaxDynamicSharedMemorySize, GSMEM_GU);
    cudaFuncSetAttribute(down_gemm, cudaFuncAttributeMaxDynamicSharedMemorySize, GSMEM_DN);

    int* d_count; cudaGetSymbolAddress((void**)&d_count, g_count);
    cudaMemsetAsync(d_count, 0, NEXP * sizeof(int), 0);
    cudaMemsetAsync(out, 0, main_sz * sizeof(float), 0);

    router_kernel<<<T, 128>>>(x, gw, logits, T);
    dispatch_kernel<<<1, 1024>>>(T);

    int mtiles = (T + 127) / 128;
    float* d_gu; cudaGetSymbolAddress((void**)&d_gu, g_gu);
    ushort_t *d_xh, *d_xl, *d_h16;
    cudaGetSymbolAddress((void**)&d_xh, g_x_hi);
    cudaGetSymbolAddress((void**)&d_xl, g_x_lo);
    cudaGetSymbolAddress((void**)&d_h16, g_h16);

    dim3 gu_grid(mtiles, TWO_I / 128, NEXP);
    gu_gemm<<<gu_grid, 256, GSMEM_GU>>>(d_xh, d_xl, gup, d_gu);

    int npairs = 2 * T;
    swiglu_kernel<<<(npairs * (IDIM / 4) + 255) / 256, 256>>>(npairs);

    dim3 dn_grid(mtiles, HDIM / 128, NEXP);
    down_gemm<<<dn_grid, 256, GSMEM_DN>>>(d_h16, dw, out);
}